// round 12
// baseline (speedup 1.0000x reference)
#include <cuda_runtime.h>
#include <cuda_fp16.h>
#include <cstdint>

// Problem constants: N_UNIQUE=10000, N_BASES=10, FILTERS=16, B=32, L=100000
#define N_UNIQUE 10000
#define N_BASES  10
#define FILTERS  16
#define N_ELEMS  (32 * 100000)            // 3,200,000
#define TPB      1024
#define UNROLL   4
#define N_SLICES 74
#define SLICE    43244                    // ceil(3.2e6 / 74)
#define GATHER_BLOCKS (N_SLICES * 4)      // 296 = 2 blocks/SM, 4 quarters x 74 slices
#define SMEM_BYTES (N_UNIQUE * 8)         // 80,000 B: fp16 quarter-table (4 filters/row)

// Quarter-sharded fp16 table (bias folded in): g_tabq[q][u][c] = filter 4q+c.
__device__ __half g_tabq[4][N_UNIQUE][4];

// Kernel 1: tab = X_spline @ kernel + bias, quantized to fp16, quarter-major.
__global__ void precompute_shrunk(const float* __restrict__ X_spline,
                                  const float* __restrict__ kern,
                                  const float* __restrict__ bias) {
    int t = blockIdx.x * blockDim.x + threadIdx.x;   // over 160000 scalars
    if (t >= N_UNIQUE * FILTERS) return;
    int u = t >> 4;
    int f = t & 15;
    float acc = __ldg(bias + f);
#pragma unroll
    for (int b = 0; b < N_BASES; ++b)
        acc = fmaf(__ldg(X_spline + u * N_BASES + b), __ldg(kern + b * FILTERS + f), acc);
    g_tabq[f >> 2][u][f & 3] = __float2half_rn(acc);
}

// Kernel 2: block (slice s, quarter q) holds the 80KB fp16 quarter-table in
// SMEM (2 CTAs/SM => 64 warps/SM). Lane = one element: coalesced idx LDG.32
// (128B/warp), random LDS.64 gather, cvt to float4, one 16B streaming store
// at out4[e*4+q].
__global__ __launch_bounds__(TPB, 2) void gather_out(const int* __restrict__ idx,
                                                     float4* __restrict__ out4) {
    extern __shared__ uint2 tab[];                    // [N_UNIQUE] 8B entries
    const unsigned tid = threadIdx.x;
    const unsigned q   = blockIdx.x & 3u;
    const unsigned s   = blockIdx.x >> 2;

    // Fill the 80KB quarter table (contiguous 16B loads, fully coalesced).
    {
        const uint4* src = reinterpret_cast<const uint4*>(g_tabq[q]);
        uint4* dst = reinterpret_cast<uint4*>(tab);
        for (unsigned t = tid; t < N_UNIQUE / 2; t += TPB)
            dst[t] = __ldg(src + t);
    }
    __syncthreads();

    const unsigned eBeg = s * SLICE;
    const unsigned eEnd = (eBeg + SLICE < N_ELEMS) ? (eBeg + SLICE) : N_ELEMS;

    for (unsigned base = eBeg + tid; base < eEnd; base += TPB * UNROLL) {
        // Phase 1: 4 independent coalesced idx loads (front-batched).
        int u[UNROLL];
#pragma unroll
        for (int k = 0; k < UNROLL; ++k) {
            unsigned e = base + k * TPB;
            u[k] = (e < eEnd) ? __ldg(idx + e) : 0;
        }
        // Phase 2: 4 independent SMEM gathers (8B each, off the LTS path).
        uint2 hv[UNROLL];
#pragma unroll
        for (int k = 0; k < UNROLL; ++k)
            hv[k] = tab[(unsigned)u[k]];
        // Phase 3: convert fp16->fp32, streaming 16B stores.
#pragma unroll
        for (int k = 0; k < UNROLL; ++k) {
            unsigned e = base + k * TPB;
            if (e < eEnd) {
                float2 lo = __half22float2(*reinterpret_cast<__half2*>(&hv[k].x));
                float2 hi = __half22float2(*reinterpret_cast<__half2*>(&hv[k].y));
                __stcs(out4 + ((size_t)e * 4u + q),
                       make_float4(lo.x, lo.y, hi.x, hi.y));
            }
        }
    }
}

extern "C" void kernel_launch(void* const* d_in, const int* in_sizes, int n_in,
                              void* d_out, int out_size) {
    // Identify inputs by element count (all distinct):
    // idx: 3,200,000 | X_spline: 100,000 | kernel: 160 | bias: 16
    const int*   idx      = nullptr;
    const float* X_spline = nullptr;
    const float* kern     = nullptr;
    const float* bias     = nullptr;
    for (int i = 0; i < n_in; ++i) {
        switch (in_sizes[i]) {
            case N_ELEMS:             idx      = (const int*)  d_in[i]; break;
            case N_UNIQUE * N_BASES:  X_spline = (const float*)d_in[i]; break;
            case N_BASES * FILTERS:   kern     = (const float*)d_in[i]; break;
            case FILTERS:             bias     = (const float*)d_in[i]; break;
            default: break;
        }
    }

    static bool attr_done = false;
    if (!attr_done) {
        cudaFuncSetAttribute(gather_out,
                             cudaFuncAttributeMaxDynamicSharedMemorySize,
                             SMEM_BYTES);
        attr_done = true;
    }

    {
        int total = N_UNIQUE * FILTERS;
        precompute_shrunk<<<(total + 255) / 256, 256>>>(X_spline, kern, bias);
    }
    gather_out<<<GATHER_BLOCKS, TPB, SMEM_BYTES>>>(idx, (float4*)d_out);
}

// round 13
// speedup vs baseline: 2.3757x; 2.3757x over previous
#include <cuda_runtime.h>

// Problem constants: N_UNIQUE=10000, N_BASES=10, FILTERS=16, B=32, L=100000
#define N_UNIQUE 10000
#define N_BASES  10
#define FILTERS  16
#define N_ELEMS  (32 * 100000)           // 3,200,000
#define N_OUT4   (N_ELEMS * 4)           // 12,800,000 float4 outputs
#define UNROLL   4
#define TPB      256
#define GATHER_BLOCKS (N_OUT4 / (TPB * UNROLL))   // 12500 exactly, no tail

// Precomputed bias-fused unique-value table, fp32 (device global scratch).
__device__ float4 g_shrunk4[N_UNIQUE * 4];   // [n_unique][16 floats] as 4x float4

// Gather load with L1 evict-last: protect the 640KB table in L1 against the
// streaming store/idx traffic (L2 policy needed v8 encoding; L1 does not).
static __device__ __forceinline__ float4 ldg_l1_keep(const float4* p) {
    float4 v;
    asm volatile("ld.global.nc.L1::evict_last.v4.f32 {%0,%1,%2,%3}, [%4];"
                 : "=f"(v.x), "=f"(v.y), "=f"(v.z), "=f"(v.w)
                 : "l"(p));
    return v;
}

// Kernel 1: shrunk_biased[u][f] = sum_b X_spline[u][b]*kernel[b][f] + bias[f]
__global__ void precompute_shrunk(const float* __restrict__ X_spline,
                                  const float* __restrict__ kern,
                                  const float* __restrict__ bias) {
    int t = blockIdx.x * blockDim.x + threadIdx.x;
    if (t >= N_UNIQUE * FILTERS) return;
    int u = t >> 4;
    int f = t & 15;
    float acc = __ldg(bias + f);
#pragma unroll
    for (int b = 0; b < N_BASES; ++b)
        acc = fmaf(__ldg(X_spline + u * N_BASES + b), __ldg(kern + b * FILTERS + f), acc);
    reinterpret_cast<float*>(g_shrunk4)[t] = acc;
}

// Kernel 2: out[e][f] = table[idx[e]][f], 4 independent chains per thread.
// float4 slot i -> element e=i>>2, quarter j=i&3: all loads/stores fully
// coalesced; each random 64B table row read cooperatively by 4 lanes.
__global__ __launch_bounds__(TPB) void gather_out(const int* __restrict__ idx,
                                                  float4* __restrict__ out4) {
    const unsigned base = blockIdx.x * (TPB * UNROLL) + threadIdx.x;

    // Phase 1: 4 independent idx loads (evict-first everywhere: read once).
    int u[UNROLL];
#pragma unroll
    for (int k = 0; k < UNROLL; ++k)
        u[k] = __ldcs(idx + ((base + k * TPB) >> 2));

    // Phase 2: 4 independent table gathers, retained in L1.
    float4 v[UNROLL];
#pragma unroll
    for (int k = 0; k < UNROLL; ++k) {
        unsigned i = base + k * TPB;
        v[k] = ldg_l1_keep(&g_shrunk4[(unsigned)u[k] * 4u + (i & 3u)]);
    }

    // Phase 3: 4 streaming stores (write-once, no L1 allocation).
#pragma unroll
    for (int k = 0; k < UNROLL; ++k)
        __stcs(out4 + (base + k * TPB), v[k]);
}

extern "C" void kernel_launch(void* const* d_in, const int* in_sizes, int n_in,
                              void* d_out, int out_size) {
    // Identify inputs by element count (all distinct):
    // idx: 3,200,000 | X_spline: 100,000 | kernel: 160 | bias: 16
    const int*   idx      = nullptr;
    const float* X_spline = nullptr;
    const float* kern     = nullptr;
    const float* bias     = nullptr;
    for (int i = 0; i < n_in; ++i) {
        switch (in_sizes[i]) {
            case N_ELEMS:             idx      = (const int*)  d_in[i]; break;
            case N_UNIQUE * N_BASES:  X_spline = (const float*)d_in[i]; break;
            case N_BASES * FILTERS:   kern     = (const float*)d_in[i]; break;
            case FILTERS:             bias     = (const float*)d_in[i]; break;
            default: break;
        }
    }

    // Give L1 the full carveout (0% smem preference) — idempotent, host-side,
    // no allocation; safe under graph capture.
    static bool attr_done = false;
    if (!attr_done) {
        cudaFuncSetAttribute(gather_out,
                             cudaFuncAttributePreferredSharedMemoryCarveout, 0);
        attr_done = true;
    }

    {
        int total = N_UNIQUE * FILTERS;
        precompute_shrunk<<<(total + TPB - 1) / TPB, TPB>>>(X_spline, kern, bias);
    }
    gather_out<<<GATHER_BLOCKS, TPB>>>(idx, (float4*)d_out);
}